// round 7
// baseline (speedup 1.0000x reference)
#include <cuda_runtime.h>
#include <cuda_bf16.h>

#define N_PTS   4096
#define NSAMPLE 9
#define TOPK    5
#define R2      0.01f
#define H2      0.0144f
#define EPS_    1e-12f
#define MAXB    8
#define GRID_D  10
#define NCELL   1000
#define IMAX    0x7fffffff

#define LPQ     8                          // lanes per query
#define QPB     16                         // queries per block
#define TPB_G   (QPB * LPQ)                // 128 threads
#define GBLK_PER_BATCH (N_PTS / QPB)       // 256 blocks per batch

// cell-sorted points: xyz + original index in .w
__device__ float4 g_pts[MAXB * N_PTS];
__device__ int    g_cs [MAXB * (NCELL + 1)];
__device__ float  g_partials[MAXB * GBLK_PER_BATCH];
__device__ unsigned int g_ticket;   // zero-init; reset by last block each launch

// ---------------- Kernel A: counting sort into cells (1 block / batch) ------
// dyn smem: stash float4[4096] (64K) | hist int[1024] (4K) | cstart int[1024] (4K) | wsum int[32]
#define BIN_SMEM (65536 + 4096 + 4096 + 128)

__global__ void __launch_bounds__(1024)
density_bin(const float* __restrict__ pred) {
    extern __shared__ char smem[];
    float4* stash  = (float4*)smem;
    int*    hist   = (int*)(smem + 65536);
    int*    cstart = (int*)(smem + 69632);
    int*    wsum   = (int*)(smem + 73728);

    const int b    = blockIdx.x;
    const int tid  = threadIdx.x;
    const int lane = tid & 31;
    const int wid  = tid >> 5;
    const float* pb = pred + (size_t)b * N_PTS * 3;

    if (tid < NCELL) hist[tid] = 0;
    __syncthreads();

#pragma unroll
    for (int it = 0; it < N_PTS / 1024; it++) {
        const int i = it * 1024 + tid;
        float x = pb[i * 3 + 0], y = pb[i * 3 + 1], z = pb[i * 3 + 2];
        int cx = min((int)(x * 10.0f), GRID_D - 1);
        int cy = min((int)(y * 10.0f), GRID_D - 1);
        int cz = min((int)(z * 10.0f), GRID_D - 1);
        int c = cz * 100 + cy * 10 + cx;
        stash[i] = make_float4(x, y, z, __int_as_float(c));
        atomicAdd(&hist[c], 1);
    }
    __syncthreads();

    // warp-shuffle inclusive scan over 1024 slots
    int x = (tid < NCELL) ? hist[tid] : 0;
#pragma unroll
    for (int off = 1; off < 32; off <<= 1) {
        int y = __shfl_up_sync(0xffffffffu, x, off);
        if (lane >= off) x += y;
    }
    if (lane == 31) wsum[wid] = x;
    __syncthreads();
    if (wid == 0) {
        int ws = wsum[lane];
        int wx = ws;
#pragma unroll
        for (int off = 1; off < 32; off <<= 1) {
            int y = __shfl_up_sync(0xffffffffu, wx, off);
            if (lane >= off) wx += y;
        }
        wsum[lane] = wx - ws;
    }
    __syncthreads();
    const int incl = x + wsum[wid];

    if (tid == 0) { cstart[0] = 0; g_cs[b * (NCELL + 1)] = 0; }
    if (tid < NCELL) {
        cstart[tid + 1] = incl;
        g_cs[b * (NCELL + 1) + tid + 1] = incl;
        hist[tid] = 0;   // reuse as cursor
    }
    __syncthreads();

#pragma unroll
    for (int it = 0; it < N_PTS / 1024; it++) {
        const int i = it * 1024 + tid;
        float4 f = stash[i];
        int c = __float_as_int(f.w);
        int pos = cstart[c] + atomicAdd(&hist[c], 1);
        g_pts[b * N_PTS + pos] = make_float4(f.x, f.y, f.z, __int_as_float(i));
    }
}

// ---------------- Kernel B: octet-cooperative ball query + topk + loss -----
__global__ void __launch_bounds__(TPB_G)
density_group(float* __restrict__ out, float inv_count) {
    __shared__ float red[TPB_G / 32];
    __shared__ int   is_last;

    const int b     = blockIdx.x / GBLK_PER_BATCH;
    const int blk   = blockIdx.x % GBLK_PER_BATCH;
    const int goff  = b * N_PTS;
    const int csoff = b * (NCELL + 1);

    const int tid    = threadIdx.x;
    const int lane   = tid & 31;
    const int tq     = tid & (LPQ - 1);      // lane within octet
    const int qlocal = tid / LPQ;            // query within block
    const int t      = blk * QPB + qlocal;   // query in sorted order

    const float4 q = __ldg(&g_pts[goff + t]);

    const int cy = min((int)(q.y * 10.0f), GRID_D - 1);
    const int cz = min((int)(q.z * 10.0f), GRID_D - 1);
    const int y0 = max(cy - 1, 0), y1 = min(cy + 1, GRID_D - 1);
    const int z0 = max(cz - 1, 0), z1 = min(cz + 1, GRID_D - 1);

    // per-lane: 9 smallest original indices among this lane's candidates
    int   idx9[NSAMPLE];
    float val9[NSAMPLE];
#pragma unroll
    for (int k = 0; k < NSAMPLE; k++) { idx9[k] = IMAX; val9[k] = 0.0f; }

    for (int zz = z0; zz <= z1; zz++) {
        const float dzb = fmaxf(0.0f, fmaxf(zz * 0.1f - q.z, q.z - (zz + 1) * 0.1f));
        const float dz2 = dzb * dzb;
        for (int yy = y0; yy <= y1; yy++) {
            const float dyb = fmaxf(0.0f, fmaxf(yy * 0.1f - q.y, q.y - (yy + 1) * 0.1f));
            const float rem = R2 + 1e-7f - fmaf(dyb, dyb, dz2);
            if (rem < 0.0f) continue;                 // row can't contain in-ball pts
            const float dxm = sqrtf(rem);             // max |px - qx| for this row
            const int xa = max(0, (int)((q.x - dxm) * 10.0f));
            const int xb = min(GRID_D - 1, (int)((q.x + dxm) * 10.0f));

            const int rowbase = zz * 100 + yy * 10;
            const int jb = __ldg(&g_cs[csoff + rowbase + xa]);
            const int je = __ldg(&g_cs[csoff + rowbase + xb + 1]);

            // software-pipelined candidate loop (prefetch next float4)
            int j = jb + tq;
            bool have = j < je;
            float4 pn;
            if (have) pn = __ldg(&g_pts[goff + j]);
            while (have) {
                const float4 p = pn;
                const int jn = j + LPQ;
                have = jn < je;
                if (have) pn = __ldg(&g_pts[goff + jn]);
                j = jn;

                float dx  = q.x - p.x;
                float dy  = q.y - p.y;
                float dzp = q.z - p.z;
                float d2 = fmaf(dx, dx, fmaf(dy, dy, dzp * dzp));
                if (d2 <= R2) {
                    int ci = __float_as_int(p.w);
                    if (ci < idx9[NSAMPLE - 1]) {
                        float cv = d2;
#pragma unroll
                        for (int k = 0; k < NSAMPLE; k++) {
                            if (ci < idx9[k]) {
                                int   ti = idx9[k]; idx9[k] = ci; ci = ti;
                                float tv = val9[k]; val9[k] = cv; cv = tv;
                            }
                        }
                    }
                }
            }
        }
    }

    // octet merge: 9 pop-min rounds over the 8 sorted per-lane lists.
    // Indices are unique, so exactly one lane pops per round (or none at IMAX).
    int   mi9[NSAMPLE];
    float m9 [NSAMPLE];
#pragma unroll
    for (int k = 0; k < NSAMPLE; k++) {
        int   bi = idx9[0];
        float bv = val9[0];
#pragma unroll
        for (int stp = 1; stp < LPQ; stp <<= 1) {
            int   oi = __shfl_xor_sync(0xffffffffu, bi, stp);
            float ov = __shfl_xor_sync(0xffffffffu, bv, stp);
            if (oi < bi) { bi = oi; bv = ov; }
        }
        mi9[k] = bi;
        m9 [k] = bv;
        if (idx9[0] == bi && bi != IMAX) {   // this lane pops its head
#pragma unroll
            for (int s = 0; s < NSAMPLE - 1; s++) {
                idx9[s] = idx9[s + 1];
                val9[s] = val9[s + 1];
            }
            idx9[NSAMPLE - 1] = IMAX;
        }
    }

    // epilogue on octet leader only
    float acc = 0.0f;
    if (tq == 0) {
        const float v0 = m9[0];              // self always in-ball
#pragma unroll
        for (int k = 1; k < NSAMPLE; k++)
            if (mi9[k] == IMAX) m9[k] = v0;

#pragma unroll
        for (int i = 0; i < TOPK; i++) {
            int   mi = i;
            float mv = m9[i];
#pragma unroll
            for (int j = i + 1; j < NSAMPLE; j++)
                if (m9[j] < mv) { mv = m9[j]; mi = j; }
            m9[mi] = m9[i];
            m9[i]  = mv;
            if (i >= 1) {
                float ds = mv < EPS_ ? EPS_ : mv;
                acc += 0.1f - sqrtf(ds) * __expf(-ds * (1.0f / H2));
            }
        }
    }

    // deterministic block reduction (non-leader lanes contribute 0)
#pragma unroll
    for (int off = 16; off > 0; off >>= 1)
        acc += __shfl_down_sync(0xffffffffu, acc, off);
    const int wid = tid >> 5;
    if (lane == 0) red[wid] = acc;
    __syncthreads();
    if (tid == 0) {
        float s = 0.0f;
#pragma unroll
        for (int w = 0; w < TPB_G / 32; w++) s += red[w];
        g_partials[blockIdx.x] = s;
        __threadfence();
        unsigned tk = atomicAdd(&g_ticket, 1u);
        is_last = (tk == gridDim.x - 1) ? 1 : 0;
    }
    __syncthreads();

    if (is_last && tid < 32) {
        const int nb = gridDim.x;
        float s = 0.0f;
        for (int i = lane; i < nb; i += 32) s += g_partials[i];
#pragma unroll
        for (int off = 16; off > 0; off >>= 1)
            s += __shfl_down_sync(0xffffffffu, s, off);
        if (lane == 0) {
            out[0] = s * inv_count;
            g_ticket = 0;
        }
    }
}

extern "C" void kernel_launch(void* const* d_in, const int* in_sizes, int n_in,
                              void* d_out, int out_size) {
    const float* pred = (const float*)d_in[0];
    const int B = in_sizes[0] / (N_PTS * 3);
    const int nblocks = B * GBLK_PER_BATCH;

    cudaFuncSetAttribute(density_bin,
                         cudaFuncAttributeMaxDynamicSharedMemorySize, BIN_SMEM);

    density_bin<<<B, 1024, BIN_SMEM>>>(pred);

    const float inv_count = 1.0f / (float)((long long)B * N_PTS * (TOPK - 1));
    density_group<<<nblocks, TPB_G>>>((float*)d_out, inv_count);
}

// round 8
// speedup vs baseline: 1.2482x; 1.2482x over previous
#include <cuda_runtime.h>
#include <cuda_bf16.h>

#define N_PTS   4096
#define NSAMPLE 9
#define TOPK    5
#define R2      0.01f
#define H2      0.0144f
#define EPS_    1e-12f
#define MAXB    8
#define GRID_D  10
#define NCELL   1000
#define IMAX    0x7fffffff

#define LPQ     4                          // lanes per query
#define QPB     32                         // queries per block
#define TPB_G   (QPB * LPQ)                // 128 threads
#define GBLK_PER_BATCH (N_PTS / QPB)       // 128 blocks per batch

// cell-sorted points: xyz + original index in .w
__device__ float4 g_pts[MAXB * N_PTS];
// points by ORIGINAL index (for value recomputation in the epilogue)
__device__ float4 g_org[MAXB * N_PTS];
__device__ int    g_cs [MAXB * (NCELL + 1)];
__device__ float  g_partials[MAXB * GBLK_PER_BATCH];
__device__ unsigned int g_ticket;   // zero-init; reset by last block each launch

// ---------------- Kernel A: counting sort into cells (1 block / batch) ------
// dyn smem: stash float4[4096] (64K) | hist int[1024] (4K) | cstart int[1024] (4K) | wsum int[32]
#define BIN_SMEM (65536 + 4096 + 4096 + 128)

__global__ void __launch_bounds__(1024)
density_bin(const float* __restrict__ pred) {
    extern __shared__ char smem[];
    float4* stash  = (float4*)smem;
    int*    hist   = (int*)(smem + 65536);
    int*    cstart = (int*)(smem + 69632);
    int*    wsum   = (int*)(smem + 73728);

    const int b    = blockIdx.x;
    const int tid  = threadIdx.x;
    const int lane = tid & 31;
    const int wid  = tid >> 5;
    const float* pb = pred + (size_t)b * N_PTS * 3;

    if (tid < NCELL) hist[tid] = 0;
    __syncthreads();

#pragma unroll
    for (int it = 0; it < N_PTS / 1024; it++) {
        const int i = it * 1024 + tid;
        float x = pb[i * 3 + 0], y = pb[i * 3 + 1], z = pb[i * 3 + 2];
        int cx = min((int)(x * 10.0f), GRID_D - 1);
        int cy = min((int)(y * 10.0f), GRID_D - 1);
        int cz = min((int)(z * 10.0f), GRID_D - 1);
        int c = cz * 100 + cy * 10 + cx;
        stash[i] = make_float4(x, y, z, __int_as_float(c));
        g_org[b * N_PTS + i] = make_float4(x, y, z, 0.0f);
        atomicAdd(&hist[c], 1);
    }
    __syncthreads();

    // warp-shuffle inclusive scan over 1024 slots
    int x = (tid < NCELL) ? hist[tid] : 0;
#pragma unroll
    for (int off = 1; off < 32; off <<= 1) {
        int y = __shfl_up_sync(0xffffffffu, x, off);
        if (lane >= off) x += y;
    }
    if (lane == 31) wsum[wid] = x;
    __syncthreads();
    if (wid == 0) {
        int ws = wsum[lane];
        int wx = ws;
#pragma unroll
        for (int off = 1; off < 32; off <<= 1) {
            int y = __shfl_up_sync(0xffffffffu, wx, off);
            if (lane >= off) wx += y;
        }
        wsum[lane] = wx - ws;
    }
    __syncthreads();
    const int incl = x + wsum[wid];

    if (tid == 0) { cstart[0] = 0; g_cs[b * (NCELL + 1)] = 0; }
    if (tid < NCELL) {
        cstart[tid + 1] = incl;
        g_cs[b * (NCELL + 1) + tid + 1] = incl;
        hist[tid] = 0;   // reuse as cursor
    }
    __syncthreads();

#pragma unroll
    for (int it = 0; it < N_PTS / 1024; it++) {
        const int i = it * 1024 + tid;
        float4 f = stash[i];
        int c = __float_as_int(f.w);
        int pos = cstart[c] + atomicAdd(&hist[c], 1);
        g_pts[b * N_PTS + pos] = make_float4(f.x, f.y, f.z, __int_as_float(i));
    }
}

// ---------------- Kernel B: quad-cooperative, index-only selection ---------
__global__ void __launch_bounds__(TPB_G)
density_group(float* __restrict__ out, float inv_count) {
    __shared__ float red[TPB_G / 32];
    __shared__ int   is_last;

    const int b     = blockIdx.x / GBLK_PER_BATCH;
    const int blk   = blockIdx.x % GBLK_PER_BATCH;
    const int goff  = b * N_PTS;
    const int csoff = b * (NCELL + 1);

    const int tid    = threadIdx.x;
    const int lane   = tid & 31;
    const int tq     = tid & (LPQ - 1);      // lane within quad
    const int qlocal = tid >> 2;             // query within block
    const int t      = blk * QPB + qlocal;   // query in sorted order

    const float4 q = __ldg(&g_pts[goff + t]);

    const int cy = min((int)(q.y * 10.0f), GRID_D - 1);
    const int cz = min((int)(q.z * 10.0f), GRID_D - 1);
    const int y0 = max(cy - 1, 0), y1 = min(cy + 1, GRID_D - 1);
    const int z0 = max(cz - 1, 0), z1 = min(cz + 1, GRID_D - 1);

    // per-lane: 9 smallest original indices among this lane's candidates
    int idx9[NSAMPLE];
#pragma unroll
    for (int k = 0; k < NSAMPLE; k++) idx9[k] = IMAX;

    for (int zz = z0; zz <= z1; zz++) {
        const float dzb = fmaxf(0.0f, fmaxf(zz * 0.1f - q.z, q.z - (zz + 1) * 0.1f));
        const float dz2 = dzb * dzb;
        for (int yy = y0; yy <= y1; yy++) {
            const float dyb = fmaxf(0.0f, fmaxf(yy * 0.1f - q.y, q.y - (yy + 1) * 0.1f));
            const float rem = R2 + 1e-7f - fmaf(dyb, dyb, dz2);
            if (rem < 0.0f) continue;                 // row can't contain in-ball pts
            const float dxm = sqrtf(rem);             // max |px - qx| for this row
            const int xa = max(0, (int)((q.x - dxm) * 10.0f));
            const int xb = min(GRID_D - 1, (int)((q.x + dxm) * 10.0f));

            const int rowbase = zz * 100 + yy * 10;
            const int jb = __ldg(&g_cs[csoff + rowbase + xa]);
            const int je = __ldg(&g_cs[csoff + rowbase + xb + 1]);

            // software-pipelined candidate loop (prefetch next float4)
            int j = jb + tq;
            bool have = j < je;
            float4 pn;
            if (have) pn = __ldg(&g_pts[goff + j]);
            while (have) {
                const float4 p = pn;
                const int jn = j + LPQ;
                have = jn < je;
                if (have) pn = __ldg(&g_pts[goff + jn]);
                j = jn;

                float dx  = q.x - p.x;
                float dy  = q.y - p.y;
                float dzp = q.z - p.z;
                float d2 = fmaf(dx, dx, fmaf(dy, dy, dzp * dzp));
                if (d2 <= R2) {
                    int ci = __float_as_int(p.w);
                    if (ci < idx9[NSAMPLE - 1]) {       // index-only 9-deep insert
#pragma unroll
                        for (int k = 0; k < NSAMPLE; k++) {
                            if (ci < idx9[k]) { int ti = idx9[k]; idx9[k] = ci; ci = ti; }
                        }
                    }
                }
            }
        }
    }

    // quad merge (indices only): 9 pop-min rounds over 4 sorted per-lane lists
    int mi9[NSAMPLE];
#pragma unroll
    for (int k = 0; k < NSAMPLE; k++) {
        int bi = idx9[0];
        int oi = __shfl_xor_sync(0xffffffffu, bi, 1);
        bi = min(bi, oi);
        oi = __shfl_xor_sync(0xffffffffu, bi, 2);
        bi = min(bi, oi);
        mi9[k] = bi;
        if (idx9[0] == bi && bi != IMAX) {   // this lane pops its head
#pragma unroll
            for (int s = 0; s < NSAMPLE - 1; s++) idx9[s] = idx9[s + 1];
            idx9[NSAMPLE - 1] = IMAX;
        }
    }

    // epilogue on quad leader: recompute the 9 values (bit-identical fmaf form),
    // padding handled by substituting mi9[0] for IMAX slots before the load.
    float acc = 0.0f;
    if (tq == 0) {
        float m9[NSAMPLE];
#pragma unroll
        for (int k = 0; k < NSAMPLE; k++) {
            const int ik = (mi9[k] == IMAX) ? mi9[0] : mi9[k];
            const float4 p = __ldg(&g_org[goff + ik]);
            float dx  = q.x - p.x;
            float dy  = q.y - p.y;
            float dzp = q.z - p.z;
            m9[k] = fmaf(dx, dx, fmaf(dy, dy, dzp * dzp));
        }

#pragma unroll
        for (int i = 0; i < TOPK; i++) {
            int   mi = i;
            float mv = m9[i];
#pragma unroll
            for (int j = i + 1; j < NSAMPLE; j++)
                if (m9[j] < mv) { mv = m9[j]; mi = j; }
            m9[mi] = m9[i];
            m9[i]  = mv;
            if (i >= 1) {
                float ds = mv < EPS_ ? EPS_ : mv;
                acc += 0.1f - sqrtf(ds) * __expf(-ds * (1.0f / H2));
            }
        }
    }

    // deterministic block reduction (non-leader lanes contribute 0)
#pragma unroll
    for (int off = 16; off > 0; off >>= 1)
        acc += __shfl_down_sync(0xffffffffu, acc, off);
    const int wid = tid >> 5;
    if (lane == 0) red[wid] = acc;
    __syncthreads();
    if (tid == 0) {
        float s = 0.0f;
#pragma unroll
        for (int w = 0; w < TPB_G / 32; w++) s += red[w];
        g_partials[blockIdx.x] = s;
        __threadfence();
        unsigned tk = atomicAdd(&g_ticket, 1u);
        is_last = (tk == gridDim.x - 1) ? 1 : 0;
    }
    __syncthreads();

    if (is_last && tid < 32) {
        const int nb = gridDim.x;
        float s = 0.0f;
        for (int i = lane; i < nb; i += 32) s += g_partials[i];
#pragma unroll
        for (int off = 16; off > 0; off >>= 1)
            s += __shfl_down_sync(0xffffffffu, s, off);
        if (lane == 0) {
            out[0] = s * inv_count;
            g_ticket = 0;
        }
    }
}

extern "C" void kernel_launch(void* const* d_in, const int* in_sizes, int n_in,
                              void* d_out, int out_size) {
    const float* pred = (const float*)d_in[0];
    const int B = in_sizes[0] / (N_PTS * 3);
    const int nblocks = B * GBLK_PER_BATCH;

    cudaFuncSetAttribute(density_bin,
                         cudaFuncAttributeMaxDynamicSharedMemorySize, BIN_SMEM);

    density_bin<<<B, 1024, BIN_SMEM>>>(pred);

    const float inv_count = 1.0f / (float)((long long)B * N_PTS * (TOPK - 1));
    density_group<<<nblocks, TPB_G>>>((float*)d_out, inv_count);
}